// round 1
// baseline (speedup 1.0000x reference)
#include <cuda_runtime.h>
#include <math.h>

#define NN 50000
#define EE 1200000
#define GG 256

// ---------------- scratch (static device allocations are allowed) -----------
__device__ float g_hx[NN * 64];      // x @ conv1_W
__device__ float g_h[NN * 64];       // running node features
__device__ float g_u[NN * 64];       // LN+PReLU output per layer
__device__ float g_agg[NN * 64];     // GEN aggregation output
__device__ float g_z1[NN * 128];     // MLP hidden
__device__ float g_xcat[NN * 256];   // JK concat buffer
__device__ int   g_hist[NN];
__device__ int   g_fill[NN];
__device__ int   g_rowptr[NN + 1];
__device__ int   g_colsrc[EE];
__device__ float g_dinv[NN];
__device__ float    g_psum[GG * 256];
__device__ unsigned g_pmax[GG * 256];
__device__ float    g_cnt[GG];

__device__ __forceinline__ unsigned enc_f(float f) {
    unsigned b = __float_as_uint(f);
    return (b >> 31) ? ~b : (b | 0x80000000u);
}
__device__ __forceinline__ float dec_f(unsigned u) {
    unsigned b = (u >> 31) ? (u ^ 0x80000000u) : ~u;
    return __uint_as_float(b);
}

// ---------------- init ------------------------------------------------------
__global__ void k_init() {
    int i = blockIdx.x * blockDim.x + threadIdx.x;
    int st = gridDim.x * blockDim.x;
    for (int j = i; j < NN; j += st) { g_hist[j] = 0; g_fill[j] = 0; }
    for (int j = i; j < GG * 256; j += st) { g_psum[j] = 0.f; g_pmax[j] = 0x007FFFFFu; }  // enc(-inf)
    for (int j = i; j < GG; j += st) g_cnt[j] = 0.f;
}

// ---------------- CSR build -------------------------------------------------
__global__ void k_hist(const int* __restrict__ dst) {
    int i = blockIdx.x * blockDim.x + threadIdx.x;
    if (i < EE) atomicAdd(&g_hist[dst[i]], 1);
}

__global__ void k_scan() {  // single block, 1024 threads
    __shared__ int ssum[1024];
    int tid = threadIdx.x;
    const int chunk = (NN + 1023) / 1024;
    int beg = tid * chunk;
    int end = min(beg + chunk, NN);
    int s = 0;
    for (int i = beg; i < end; i++) s += g_hist[i];
    ssum[tid] = s;
    __syncthreads();
    for (int off = 1; off < 1024; off <<= 1) {
        int v = (tid >= off) ? ssum[tid - off] : 0;
        __syncthreads();
        ssum[tid] += v;
        __syncthreads();
    }
    int run = ssum[tid] - s;  // exclusive base
    for (int i = beg; i < end; i++) {
        g_rowptr[i] = run;
        run += g_hist[i];
        g_dinv[i] = rsqrtf((float)(g_hist[i] + 1));  // deg = indeg + self-loop
    }
    if (tid == 0) g_rowptr[NN] = EE;
}

__global__ void k_scatter(const int* __restrict__ src, const int* __restrict__ dst) {
    int i = blockIdx.x * blockDim.x + threadIdx.x;
    if (i < EE) {
        int d = dst[i];
        int pos = g_rowptr[d] + atomicAdd(&g_fill[d], 1);
        g_colsrc[pos] = src[i];
    }
}

// ---------------- x @ conv1_W (N x 5 x 64) ----------------------------------
__global__ void k_hx(const float* __restrict__ x, const float* __restrict__ W) {
    int idx = blockIdx.x * blockDim.x + threadIdx.x;
    if (idx >= NN * 64) return;
    int n = idx >> 6, c = idx & 63;
    float a = 0.f;
#pragma unroll
    for (int f = 0; f < 5; f++) a += x[n * 5 + f] * W[f * 64 + c];
    g_hx[idx] = a;
}

// ---------------- GCNConv aggregate + BN + ReLU -----------------------------
__global__ void k_gcn(const float* __restrict__ cb, const float* __restrict__ bg,
                      const float* __restrict__ bb) {
    int tid = threadIdx.x;
    int n = blockIdx.x * 4 + (tid >> 6);
    int c = tid & 63;
    if (n >= NN) return;
    float acc = 0.f;
    int b = g_rowptr[n], e = g_rowptr[n + 1];
    for (int i = b; i < e; i++) {
        int s = g_colsrc[i];
        acc += g_hx[s * 64 + c] * g_dinv[s];
    }
    float dn = g_dinv[n];
    acc = (acc + g_hx[n * 64 + c] * dn) * dn + cb[c];
    const float BNS = rsqrtf(1.f + 1e-5f);
    acc = acc * (bg[c] * BNS) + bb[c];
    acc = fmaxf(acc, 0.f);
    g_h[n * 64 + c] = acc;
    g_xcat[n * 256 + c] = acc;
}

// ---------------- LayerNorm + PReLU -----------------------------------------
__global__ void k_ln(const float* __restrict__ g, const float* __restrict__ b,
                     const float* __restrict__ a) {
    int tid = threadIdx.x;
    int n = blockIdx.x * 8 + (tid >> 5);
    int l = tid & 31;
    if (n >= NN) return;
    float v0 = g_h[n * 64 + l];
    float v1 = g_h[n * 64 + l + 32];
    float s = v0 + v1;
    float q = v0 * v0 + v1 * v1;
#pragma unroll
    for (int off = 16; off > 0; off >>= 1) {
        s += __shfl_xor_sync(0xffffffffu, s, off);
        q += __shfl_xor_sync(0xffffffffu, q, off);
    }
    float mu = s * (1.f / 64.f);
    float var = q * (1.f / 64.f) - mu * mu;
    float rs = rsqrtf(var + 1e-5f);
    float y0 = (v0 - mu) * rs * g[l] + b[l];
    y0 = (y0 >= 0.f) ? y0 : a[l] * y0;
    g_u[n * 64 + l] = y0;
    float y1 = (v1 - mu) * rs * g[l + 32] + b[l + 32];
    y1 = (y1 >= 0.f) ? y1 : a[l + 32] * y1;
    g_u[n * 64 + l + 32] = y1;
}

// ---------------- GENConv softmax aggregation (online softmax, 1 pass) ------
__global__ void k_gen(const float* __restrict__ gen_t, int layer) {
    int tid = threadIdx.x;
    int n = blockIdx.x * 4 + (tid >> 6);
    int c = tid & 63;
    if (n >= NN) return;
    float t = gen_t[layer];
    int b = g_rowptr[n], e = g_rowptr[n + 1];
    float m = -INFINITY, s = 0.f, acc = 0.f;
    for (int i = b; i < e; i++) {
        int sn = g_colsrc[i];
        float v = fmaxf(g_u[sn * 64 + c], 0.f) + 1e-7f;
        float sc = v * t;
        if (sc > m) {
            float r = __expf(m - sc);
            s *= r;
            acc *= r;
            m = sc;
        }
        float ex = __expf(sc - m);
        s += ex;
        acc += v * ex;
    }
    float out = (e > b) ? (acc / s) : 0.f;
    g_agg[n * 64 + c] = out + g_u[n * 64 + c];
}

// ---------------- MLP1: agg @ W1 + b1, BN, ReLU  (64 -> 128) ----------------
__global__ void k_mlp1(const float* __restrict__ W1, const float* __restrict__ b1,
                       const float* __restrict__ bng, const float* __restrict__ bnb) {
    __shared__ float W1s[64 * 128];   // 32 KB
    __shared__ float aS[64 * 64];     // 16 KB
    int tid = threadIdx.x;
    int n0 = blockIdx.x * 64;
    for (int i = tid; i < 64 * 128; i += 256) W1s[i] = W1[i];
    for (int i = tid; i < 64 * 64; i += 256) {
        int j = i >> 6, k = i & 63;
        int n = n0 + j;
        aS[i] = (n < NN) ? g_agg[n * 64 + k] : 0.f;
    }
    __syncthreads();
    int jt = tid >> 5;        // 0..7 -> node group
    int ot = tid & 31;        // out lane
    int j0 = jt * 8;
    float acc[8][4];
#pragma unroll
    for (int jj = 0; jj < 8; jj++)
#pragma unroll
        for (int q = 0; q < 4; q++) acc[jj][q] = 0.f;
    for (int k = 0; k < 64; k++) {
        float w0 = W1s[k * 128 + ot];
        float w1 = W1s[k * 128 + ot + 32];
        float w2 = W1s[k * 128 + ot + 64];
        float w3 = W1s[k * 128 + ot + 96];
#pragma unroll
        for (int jj = 0; jj < 8; jj++) {
            float av = aS[(j0 + jj) * 64 + k];
            acc[jj][0] += av * w0;
            acc[jj][1] += av * w1;
            acc[jj][2] += av * w2;
            acc[jj][3] += av * w3;
        }
    }
    const float BNS = rsqrtf(1.f + 1e-5f);
#pragma unroll
    for (int jj = 0; jj < 8; jj++) {
        int n = n0 + j0 + jj;
        if (n >= NN) continue;
#pragma unroll
        for (int q = 0; q < 4; q++) {
            int o = ot + 32 * q;
            float v = acc[jj][q] + b1[o];
            v = v * (bng[o] * BNS) + bnb[o];
            v = fmaxf(v, 0.f);
            g_z1[n * 128 + o] = v;
        }
    }
}

// ---------------- MLP2: z1 @ W2 + b2, residual into h, write xcat -----------
__global__ void k_mlp2(const float* __restrict__ W2, const float* __restrict__ b2,
                       int layer) {
    extern __shared__ float dyn[];
    float* W2s = dyn;          // 128*64
    float* z1S = dyn + 8192;   // 64*128
    int tid = threadIdx.x;
    int n0 = blockIdx.x * 64;
    for (int i = tid; i < 128 * 64; i += 256) W2s[i] = W2[i];
    for (int i = tid; i < 64 * 128; i += 256) {
        int j = i >> 7, k = i & 127;
        int n = n0 + j;
        z1S[i] = (n < NN) ? g_z1[n * 128 + k] : 0.f;
    }
    __syncthreads();
    int jt = tid >> 5;
    int ot = tid & 31;
    int j0 = jt * 8;
    float acc[8][2];
#pragma unroll
    for (int jj = 0; jj < 8; jj++) { acc[jj][0] = 0.f; acc[jj][1] = 0.f; }
    for (int k = 0; k < 128; k++) {
        float w0 = W2s[k * 64 + ot];
        float w1 = W2s[k * 64 + ot + 32];
#pragma unroll
        for (int jj = 0; jj < 8; jj++) {
            float av = z1S[(j0 + jj) * 128 + k];
            acc[jj][0] += av * w0;
            acc[jj][1] += av * w1;
        }
    }
#pragma unroll
    for (int jj = 0; jj < 8; jj++) {
        int n = n0 + j0 + jj;
        if (n >= NN) continue;
#pragma unroll
        for (int q = 0; q < 2; q++) {
            int o = ot + 32 * q;
            float v = acc[jj][q] + b2[o];
            float nh = g_h[n * 64 + o] + v;
            g_h[n * 64 + o] = nh;
            g_xcat[n * 256 + (layer + 1) * 64 + o] = nh;
        }
    }
}

// ---------------- pooling ----------------------------------------------------
__global__ void k_pool(const int* __restrict__ batch) {
    int n = blockIdx.x;
    int c = threadIdx.x;
    int g = batch[n];
    float v = g_xcat[n * 256 + c];
    atomicAdd(&g_psum[g * 256 + c], v);
    atomicMax(&g_pmax[g * 256 + c], enc_f(v));
    if (c == 0) atomicAdd(&g_cnt[g], 1.f);
}

// ---------------- readout MLP ------------------------------------------------
__global__ void k_readout(const float* __restrict__ W1, const float* __restrict__ b1,
                          const float* __restrict__ W2, const float* __restrict__ b2,
                          const float* __restrict__ Wo, const float* __restrict__ bo,
                          float* __restrict__ out) {
    __shared__ float p[512];
    __shared__ float q1[128];
    __shared__ float q2[64];
    int g = blockIdx.x;
    int tid = threadIdx.x;
    float cnt = fmaxf(g_cnt[g], 1.f);
    for (int i = tid; i < 256; i += 128) {
        p[i] = g_psum[g * 256 + i] / cnt;
        float mx = dec_f(g_pmax[g * 256 + i]);
        p[256 + i] = isfinite(mx) ? mx : 0.f;
    }
    __syncthreads();
    float acc = b1[tid];
    for (int k = 0; k < 512; k++) acc += p[k] * W1[k * 128 + tid];
    q1[tid] = fmaxf(acc, 0.f);
    __syncthreads();
    if (tid < 64) {
        float a2 = b2[tid];
        for (int k = 0; k < 128; k++) a2 += q1[k] * W2[k * 64 + tid];
        q2[tid] = fmaxf(a2, 0.f);
    }
    __syncthreads();
    if (tid < 32) {
        float s = q2[tid] * Wo[tid] + q2[tid + 32] * Wo[tid + 32];
#pragma unroll
        for (int off = 16; off > 0; off >>= 1) s += __shfl_xor_sync(0xffffffffu, s, off);
        if (tid == 0) out[g] = s + bo[0];
    }
}

// ---------------- launch -----------------------------------------------------
extern "C" void kernel_launch(void* const* d_in, const int* in_sizes, int n_in,
                              void* d_out, int out_size) {
    const float* x        = (const float*)d_in[0];
    const int*   ei       = (const int*)d_in[1];
    const int*   batch    = (const int*)d_in[2];
    const float* conv1_W  = (const float*)d_in[3];
    const float* conv1_b  = (const float*)d_in[4];
    const float* bn1_g    = (const float*)d_in[5];
    const float* bn1_b    = (const float*)d_in[6];
    const float* ln_g     = (const float*)d_in[7];
    const float* ln_b     = (const float*)d_in[8];
    const float* prelu_a  = (const float*)d_in[9];
    const float* gen_t    = (const float*)d_in[10];
    const float* mlp_W1   = (const float*)d_in[11];
    const float* mlp_b1   = (const float*)d_in[12];
    const float* mlp_bn_g = (const float*)d_in[13];
    const float* mlp_bn_b = (const float*)d_in[14];
    const float* mlp_W2   = (const float*)d_in[15];
    const float* mlp_b2   = (const float*)d_in[16];
    const float* lin1_W   = (const float*)d_in[17];
    const float* lin1_b   = (const float*)d_in[18];
    const float* lin2_W   = (const float*)d_in[19];
    const float* lin2_b   = (const float*)d_in[20];
    const float* out_W    = (const float*)d_in[21];
    const float* out_b    = (const float*)d_in[22];
    float* out = (float*)d_out;

    const int* src = ei;
    const int* dst = ei + EE;

    cudaFuncSetAttribute(k_mlp2, cudaFuncAttributeMaxDynamicSharedMemorySize, 65536);

    k_init<<<512, 256>>>();
    k_hist<<<(EE + 255) / 256, 256>>>(dst);
    k_scan<<<1, 1024>>>();
    k_scatter<<<(EE + 255) / 256, 256>>>(src, dst);
    k_hx<<<(NN * 64 + 255) / 256, 256>>>(x, conv1_W);
    k_gcn<<<(NN + 3) / 4, 256>>>(conv1_b, bn1_g, bn1_b);

    for (int i = 0; i < 3; i++) {
        k_ln<<<(NN + 7) / 8, 256>>>(ln_g + i * 64, ln_b + i * 64, prelu_a + i * 64);
        k_gen<<<(NN + 3) / 4, 256>>>(gen_t, i);
        k_mlp1<<<(NN + 63) / 64, 256>>>(mlp_W1 + i * 64 * 128, mlp_b1 + i * 128,
                                        mlp_bn_g + i * 128, mlp_bn_b + i * 128);
        k_mlp2<<<(NN + 63) / 64, 256, 65536>>>(mlp_W2 + i * 128 * 64, mlp_b2 + i * 64, i);
    }

    k_pool<<<NN, 256>>>(batch);
    k_readout<<<GG, 128>>>(lin1_W, lin1_b, lin2_W, lin2_b, out_W, out_b, out);
}

// round 2
// speedup vs baseline: 1.4260x; 1.4260x over previous
#include <cuda_runtime.h>
#include <math.h>

#define NN 50000
#define EE 1200000
#define GG 256
#define NBLK 196   // ceil(NN/256)

// ---------------- scratch ----------------------------------------------------
__device__ float g_hx[NN * 64];      // (x @ conv1_W) * dinv[n]
__device__ float g_h[NN * 64];       // running node features
__device__ float g_u[NN * 64];       // LN+PReLU output per layer
__device__ float g_agg[NN * 64];     // GEN aggregation output
__device__ float g_xcat[NN * 256];   // JK concat buffer
__device__ int   g_hist[NN];
__device__ int   g_fill[NN];
__device__ int   g_rowptr[NN + 1];
__device__ int   g_colsrc[EE];
__device__ float g_dinv[NN];
__device__ int   g_bsum[NBLK];
__device__ int   g_boff[NBLK];
__device__ int   g_gstart[GG + 1];

// ---------------- init ------------------------------------------------------
__global__ void k_init() {
    int i = blockIdx.x * blockDim.x + threadIdx.x;
    if (i < NN) { g_hist[i] = 0; g_fill[i] = 0; }
}

// ---------------- CSR build -------------------------------------------------
__global__ void k_hist(const int* __restrict__ dst) {
    int i = blockIdx.x * blockDim.x + threadIdx.x;
    if (i < EE) atomicAdd(&g_hist[dst[i]], 1);
}

__device__ __forceinline__ int wscan_incl(int x) {
    int lane = threadIdx.x & 31;
#pragma unroll
    for (int o = 1; o < 32; o <<= 1) {
        int y = __shfl_up_sync(0xffffffffu, x, o);
        if (lane >= o) x += y;
    }
    return x;
}

// per-block partial sums of hist
__global__ void k_part() {
    __shared__ int ws[8];
    int tid = threadIdx.x;
    int i = blockIdx.x * 256 + tid;
    int v = (i < NN) ? g_hist[i] : 0;
    int incl = wscan_incl(v);
    if ((tid & 31) == 31) ws[tid >> 5] = incl;
    __syncthreads();
    if (tid == 0) {
        int s = 0;
#pragma unroll
        for (int w = 0; w < 8; w++) s += ws[w];
        g_bsum[blockIdx.x] = s;
    }
}

// scan the NBLK block sums (1 block)
__global__ void k_scan2() {
    __shared__ int ws[8];
    int tid = threadIdx.x;
    int lane = tid & 31, w = tid >> 5;
    int v = (tid < NBLK) ? g_bsum[tid] : 0;
    int incl = wscan_incl(v);
    if (lane == 31) ws[w] = incl;
    __syncthreads();
    if (tid < 8) {
        int b = ws[tid];
#pragma unroll
        for (int o = 1; o < 8; o <<= 1) {
            int y = __shfl_up_sync(0xffu, b, o);
            if (tid >= o) b += y;
        }
        ws[tid] = b;
    }
    __syncthreads();
    int base = (w > 0) ? ws[w - 1] : 0;
    if (tid < NBLK) g_boff[tid] = base + incl - v;
    if (tid == 0) g_rowptr[NN] = EE;
}

// per-block rescan -> rowptr + dinv
__global__ void k_scan3() {
    __shared__ int ws[8];
    int tid = threadIdx.x;
    int lane = tid & 31, w = tid >> 5;
    int i = blockIdx.x * 256 + tid;
    int v = (i < NN) ? g_hist[i] : 0;
    int incl = wscan_incl(v);
    if (lane == 31) ws[w] = incl;
    __syncthreads();
    if (tid < 8) {
        int b = ws[tid];
#pragma unroll
        for (int o = 1; o < 8; o <<= 1) {
            int y = __shfl_up_sync(0xffu, b, o);
            if (tid >= o) b += y;
        }
        ws[tid] = b;
    }
    __syncthreads();
    int base = (w > 0) ? ws[w - 1] : 0;
    if (i < NN) {
        g_rowptr[i] = g_boff[blockIdx.x] + base + incl - v;
        g_dinv[i] = rsqrtf((float)(v + 1));
    }
}

__global__ void k_scatter(const int* __restrict__ src, const int* __restrict__ dst) {
    int i = blockIdx.x * blockDim.x + threadIdx.x;
    if (i < EE) {
        int d = dst[i];
        int pos = g_rowptr[d] + atomicAdd(&g_fill[d], 1);
        g_colsrc[pos] = src[i];
    }
}

// graph boundaries from sorted batch_idx
__global__ void k_gstart(const int* __restrict__ batch) {
    int n = blockIdx.x * blockDim.x + threadIdx.x;
    if (n >= NN) return;
    int b = batch[n];
    int prev = (n == 0) ? -1 : batch[n - 1];
    for (int g = prev + 1; g <= b; g++) g_gstart[g] = n;
    if (n == NN - 1) {
        for (int g = b + 1; g <= GG; g++) g_gstart[g] = NN;
    }
}

// ---------------- x @ conv1_W, pre-scaled by dinv[n] -------------------------
__global__ void k_hx(const float* __restrict__ x, const float* __restrict__ W) {
    int idx = blockIdx.x * blockDim.x + threadIdx.x;
    if (idx >= NN * 64) return;
    int n = idx >> 6, c = idx & 63;
    float a = 0.f;
#pragma unroll
    for (int f = 0; f < 5; f++) a += x[n * 5 + f] * W[f * 64 + c];
    g_hx[idx] = a * g_dinv[n];
}

// ---------------- GCNConv aggregate + BN + ReLU ------------------------------
__global__ void k_gcn(const float* __restrict__ cb, const float* __restrict__ bg,
                      const float* __restrict__ bb) {
    int tid = threadIdx.x;
    int n = blockIdx.x * 4 + (tid >> 6);
    int c = tid & 63;
    if (n >= NN) return;
    float acc = 0.f;
    int b = g_rowptr[n], e = g_rowptr[n + 1];
    int i = b;
    for (; i + 4 <= e; i += 4) {
        int s0 = g_colsrc[i], s1 = g_colsrc[i + 1];
        int s2 = g_colsrc[i + 2], s3 = g_colsrc[i + 3];
        float a0 = g_hx[s0 * 64 + c];
        float a1 = g_hx[s1 * 64 + c];
        float a2 = g_hx[s2 * 64 + c];
        float a3 = g_hx[s3 * 64 + c];
        acc += (a0 + a1) + (a2 + a3);
    }
    for (; i < e; i++) acc += g_hx[g_colsrc[i] * 64 + c];
    acc = (acc + g_hx[n * 64 + c]) * g_dinv[n] + cb[c];
    const float BNS = rsqrtf(1.f + 1e-5f);
    acc = acc * (bg[c] * BNS) + bb[c];
    acc = fmaxf(acc, 0.f);
    g_h[n * 64 + c] = acc;
    g_xcat[n * 256 + c] = acc;
}

// ---------------- LayerNorm + PReLU ------------------------------------------
__global__ void k_ln(const float* __restrict__ g, const float* __restrict__ b,
                     const float* __restrict__ a) {
    int tid = threadIdx.x;
    int n = blockIdx.x * 8 + (tid >> 5);
    int l = tid & 31;
    if (n >= NN) return;
    float v0 = g_h[n * 64 + l];
    float v1 = g_h[n * 64 + l + 32];
    float s = v0 + v1;
    float q = v0 * v0 + v1 * v1;
#pragma unroll
    for (int off = 16; off > 0; off >>= 1) {
        s += __shfl_xor_sync(0xffffffffu, s, off);
        q += __shfl_xor_sync(0xffffffffu, q, off);
    }
    float mu = s * (1.f / 64.f);
    float var = q * (1.f / 64.f) - mu * mu;
    float rs = rsqrtf(var + 1e-5f);
    float y0 = (v0 - mu) * rs * g[l] + b[l];
    y0 = (y0 >= 0.f) ? y0 : a[l] * y0;
    g_u[n * 64 + l] = y0;
    float y1 = (v1 - mu) * rs * g[l + 32] + b[l + 32];
    y1 = (y1 >= 0.f) ? y1 : a[l + 32] * y1;
    g_u[n * 64 + l + 32] = y1;
}

// ---------------- GENConv softmax aggregation (no-max, unrolled) -------------
__global__ void k_gen(const float* __restrict__ gen_t, int layer) {
    int tid = threadIdx.x;
    int n = blockIdx.x * 4 + (tid >> 6);
    int c = tid & 63;
    if (n >= NN) return;
    float t = __ldg(&gen_t[layer]);
    int b = g_rowptr[n], e = g_rowptr[n + 1];
    float s = 0.f, acc = 0.f;
    int i = b;
    for (; i + 4 <= e; i += 4) {
        int s0 = g_colsrc[i], s1 = g_colsrc[i + 1];
        int s2 = g_colsrc[i + 2], s3 = g_colsrc[i + 3];
        float v0 = fmaxf(g_u[s0 * 64 + c], 0.f) + 1e-7f;
        float v1 = fmaxf(g_u[s1 * 64 + c], 0.f) + 1e-7f;
        float v2 = fmaxf(g_u[s2 * 64 + c], 0.f) + 1e-7f;
        float v3 = fmaxf(g_u[s3 * 64 + c], 0.f) + 1e-7f;
        float e0 = __expf(v0 * t);
        float e1 = __expf(v1 * t);
        float e2 = __expf(v2 * t);
        float e3 = __expf(v3 * t);
        s += (e0 + e1) + (e2 + e3);
        acc += (v0 * e0 + v1 * e1) + (v2 * e2 + v3 * e3);
    }
    for (; i < e; i++) {
        float v = fmaxf(g_u[g_colsrc[i] * 64 + c], 0.f) + 1e-7f;
        float ex = __expf(v * t);
        s += ex;
        acc += v * ex;
    }
    float u = g_u[n * 64 + c];
    g_agg[n * 64 + c] = ((e > b) ? (acc / s) : 0.f) + u;
}

// ---------------- fused MLP: (64->128 BN ReLU ->64) + residual ---------------
__global__ void k_mlpf(const float* __restrict__ W1, const float* __restrict__ b1,
                       const float* __restrict__ bng, const float* __restrict__ bnb,
                       const float* __restrict__ W2, const float* __restrict__ b2,
                       int layer) {
    extern __shared__ float dyn[];
    float* W1s = dyn;            // 8192 floats
    float* W2s = dyn + 8192;     // 8192
    float* aS  = dyn + 16384;    // 4096
    float* z1S = dyn + 20480;    // 8192
    int tid = threadIdx.x;
    int n0 = blockIdx.x * 64;
    for (int i = tid; i < 8192; i += 256) { W1s[i] = W1[i]; W2s[i] = W2[i]; }
    for (int i = tid; i < 4096; i += 256) {
        int j = i >> 6, k = i & 63;
        int n = n0 + j;
        aS[i] = (n < NN) ? g_agg[n * 64 + k] : 0.f;
    }
    __syncthreads();
    int jt = tid >> 5;        // node group 0..7
    int ot = tid & 31;
    int j0 = jt * 8;
    // stage 1: 64 -> 128
    float acc[8][4];
#pragma unroll
    for (int jj = 0; jj < 8; jj++)
#pragma unroll
        for (int q = 0; q < 4; q++) acc[jj][q] = 0.f;
    for (int k = 0; k < 64; k++) {
        float w0 = W1s[k * 128 + ot];
        float w1 = W1s[k * 128 + ot + 32];
        float w2 = W1s[k * 128 + ot + 64];
        float w3 = W1s[k * 128 + ot + 96];
#pragma unroll
        for (int jj = 0; jj < 8; jj++) {
            float av = aS[(j0 + jj) * 64 + k];
            acc[jj][0] += av * w0;
            acc[jj][1] += av * w1;
            acc[jj][2] += av * w2;
            acc[jj][3] += av * w3;
        }
    }
    const float BNS = rsqrtf(1.f + 1e-5f);
#pragma unroll
    for (int jj = 0; jj < 8; jj++) {
#pragma unroll
        for (int q = 0; q < 4; q++) {
            int o = ot + 32 * q;
            float v = acc[jj][q] + b1[o];
            v = v * (bng[o] * BNS) + bnb[o];
            z1S[(j0 + jj) * 128 + o] = fmaxf(v, 0.f);
        }
    }
    __syncwarp();   // z1 rows of this warp written & read by this warp only
    // stage 2: 128 -> 64
    float a2[8][2];
#pragma unroll
    for (int jj = 0; jj < 8; jj++) { a2[jj][0] = 0.f; a2[jj][1] = 0.f; }
    for (int k = 0; k < 128; k++) {
        float w0 = W2s[k * 64 + ot];
        float w1 = W2s[k * 64 + ot + 32];
#pragma unroll
        for (int jj = 0; jj < 8; jj++) {
            float av = z1S[(j0 + jj) * 128 + k];
            a2[jj][0] += av * w0;
            a2[jj][1] += av * w1;
        }
    }
#pragma unroll
    for (int jj = 0; jj < 8; jj++) {
        int n = n0 + j0 + jj;
        if (n >= NN) continue;
#pragma unroll
        for (int q = 0; q < 2; q++) {
            int o = ot + 32 * q;
            float v = a2[jj][q] + b2[o];
            float nh = g_h[n * 64 + o] + v;
            g_h[n * 64 + o] = nh;
            g_xcat[n * 256 + (layer + 1) * 64 + o] = nh;
        }
    }
}

// ---------------- fused pooling + readout MLP --------------------------------
__global__ void k_poolread(const float* __restrict__ W1, const float* __restrict__ b1,
                           const float* __restrict__ W2, const float* __restrict__ b2,
                           const float* __restrict__ Wo, const float* __restrict__ bo,
                           float* __restrict__ out) {
    __shared__ float p[512];
    __shared__ float q1[128];
    __shared__ float q2[64];
    int g = blockIdx.x;
    int tid = threadIdx.x;   // 256
    int beg = g_gstart[g], end = g_gstart[g + 1];
    float sum = 0.f, mx = -INFINITY;
    for (int n = beg; n < end; n++) {
        float v = g_xcat[n * 256 + tid];
        sum += v;
        mx = fmaxf(mx, v);
    }
    float c = (float)(end - beg);
    p[tid] = sum / fmaxf(c, 1.f);
    p[256 + tid] = (end > beg) ? mx : 0.f;
    __syncthreads();
    if (tid < 128) {
        float a = b1[tid];
        for (int k = 0; k < 512; k++) a += p[k] * W1[k * 128 + tid];
        q1[tid] = fmaxf(a, 0.f);
    }
    __syncthreads();
    if (tid < 64) {
        float a = b2[tid];
        for (int k = 0; k < 128; k++) a += q1[k] * W2[k * 64 + tid];
        q2[tid] = fmaxf(a, 0.f);
    }
    __syncthreads();
    if (tid < 32) {
        float s = q2[tid] * Wo[tid] + q2[tid + 32] * Wo[tid + 32];
#pragma unroll
        for (int off = 16; off > 0; off >>= 1) s += __shfl_xor_sync(0xffffffffu, s, off);
        if (tid == 0) out[g] = s + bo[0];
    }
}

// ---------------- launch -----------------------------------------------------
extern "C" void kernel_launch(void* const* d_in, const int* in_sizes, int n_in,
                              void* d_out, int out_size) {
    const float* x        = (const float*)d_in[0];
    const int*   ei       = (const int*)d_in[1];
    const int*   batch    = (const int*)d_in[2];
    const float* conv1_W  = (const float*)d_in[3];
    const float* conv1_b  = (const float*)d_in[4];
    const float* bn1_g    = (const float*)d_in[5];
    const float* bn1_b    = (const float*)d_in[6];
    const float* ln_g     = (const float*)d_in[7];
    const float* ln_b     = (const float*)d_in[8];
    const float* prelu_a  = (const float*)d_in[9];
    const float* gen_t    = (const float*)d_in[10];
    const float* mlp_W1   = (const float*)d_in[11];
    const float* mlp_b1   = (const float*)d_in[12];
    const float* mlp_bn_g = (const float*)d_in[13];
    const float* mlp_bn_b = (const float*)d_in[14];
    const float* mlp_W2   = (const float*)d_in[15];
    const float* mlp_b2   = (const float*)d_in[16];
    const float* lin1_W   = (const float*)d_in[17];
    const float* lin1_b   = (const float*)d_in[18];
    const float* lin2_W   = (const float*)d_in[19];
    const float* lin2_b   = (const float*)d_in[20];
    const float* out_W    = (const float*)d_in[21];
    const float* out_b    = (const float*)d_in[22];
    float* out = (float*)d_out;

    const int* src = ei;
    const int* dst = ei + EE;

    static int smem_set = 0;
    if (!smem_set) {
        cudaFuncSetAttribute(k_mlpf, cudaFuncAttributeMaxDynamicSharedMemorySize, 114688);
        smem_set = 1;
    }

    k_init<<<NBLK, 256>>>();
    k_hist<<<(EE + 255) / 256, 256>>>(dst);
    k_part<<<NBLK, 256>>>();
    k_scan2<<<1, 256>>>();
    k_scan3<<<NBLK, 256>>>();
    k_scatter<<<(EE + 255) / 256, 256>>>(src, dst);
    k_gstart<<<NBLK, 256>>>(batch);
    k_hx<<<(NN * 64 + 255) / 256, 256>>>(x, conv1_W);
    k_gcn<<<(NN + 3) / 4, 256>>>(conv1_b, bn1_g, bn1_b);

    for (int i = 0; i < 3; i++) {
        k_ln<<<(NN + 7) / 8, 256>>>(ln_g + i * 64, ln_b + i * 64, prelu_a + i * 64);
        k_gen<<<(NN + 3) / 4, 256>>>(gen_t, i);
        k_mlpf<<<(NN + 63) / 64, 256, 114688>>>(mlp_W1 + i * 64 * 128, mlp_b1 + i * 128,
                                                mlp_bn_g + i * 128, mlp_bn_b + i * 128,
                                                mlp_W2 + i * 128 * 64, mlp_b2 + i * 64, i);
    }

    k_poolread<<<GG, 256>>>(lin1_W, lin1_b, lin2_W, lin2_b, out_W, out_b, out);
}